// round 5
// baseline (speedup 1.0000x reference)
#include <cuda_runtime.h>

#define NTHREADS 128
#define SPT 4                      // splines per thread (float4 width)
#define TILE_S (NTHREADS * SPT)    // 512 splines per block
#define TILE_B 32                  // batch rows per block
#define NCOEF 8                    // GRID_SIZE + SPLINE_ORDER

__global__ __launch_bounds__(NTHREADS) void bspline_kernel(
    const float* __restrict__ x,
    const float* __restrict__ coef,
    const float* __restrict__ grid,
    float* __restrict__ out,
    int nspl, int batch, int jmax)
{
    // Permuted-transposed coefficient tile.
    // Spline s0 + 4*t + i lives at slot = i*NTHREADS + t, so the LDS for
    // element i (lanes vary t) has lane-stride 1 -> conflict-free for any
    // dynamic interval index j.
    __shared__ float cT[NCOEF][TILE_S];

    const int t  = threadIdx.x;
    const int s0 = blockIdx.x * TILE_S;
    const int b0 = blockIdx.y * TILE_B;

    // Prologue: thread t loads splines s0+4t .. s0+4t+3 (64B contiguous)
    // and scatters into the permuted tile.
    #pragma unroll
    for (int i = 0; i < SPT; ++i) {
        const int s = s0 + 4 * t + i;
        const float4* cv = reinterpret_cast<const float4*>(coef + (size_t)s * NCOEF);
        const float4 cA = cv[0];
        const float4 cB = cv[1];
        const int slot = i * NTHREADS + t;
        cT[0][slot] = cA.x; cT[1][slot] = cA.y;
        cT[2][slot] = cA.z; cT[3][slot] = cA.w;
        cT[4][slot] = cB.x; cT[5][slot] = cB.y;
        cT[6][slot] = cB.z; cT[7][slot] = cB.w;
    }

    // Uniform-grid constants.
    const float g3    = __ldg(&grid[3]);
    const float inv_h = 1.0f / (__ldg(&grid[4]) - g3);
    const float c0    = -g3 * inv_h;      // t = fma(x, inv_h, c0)

    __syncthreads();

    const float4* xp = reinterpret_cast<const float4*>(x   + (size_t)b0 * nspl + s0) + t;
    float4*       op = reinterpret_cast<float4*>      (out + (size_t)b0 * nspl + s0) + t;
    const size_t rowstride4 = (size_t)nspl / 4;   // float4 elements per row

    #pragma unroll 8
    for (int bi = 0; bi < TILE_B; ++bi) {
        const float4 xv = xp[(size_t)bi * rowstride4];
        float4 res;

        #pragma unroll
        for (int i = 0; i < SPT; ++i) {
            const float xe = (i == 0) ? xv.x : (i == 1) ? xv.y : (i == 2) ? xv.z : xv.w;

            // Interval index and local coordinate.
            const float tt = fmaf(xe, inv_h, c0);
            int j = __float2int_rd(tt);
            j = max(0, min(jmax, j));
            const float u = tt - (float)j;

            // Uniform cubic B-spline weights (partition of unity for b2).
            const float omu = 1.0f - u;
            const float u2  = u * u;
            const float u3  = u2 * u;
            const float om2 = omu * omu;
            const float b0w = om2 * omu * (1.0f / 6.0f);
            const float b3w = u3 * (1.0f / 6.0f);
            const float b1w = fmaf(0.5f, u3, (2.0f / 3.0f) - u2);
            const float b2w = 1.0f - b0w - b1w - b3w;

            // Conflict-free 4-tap dot from the permuted SMEM tile.
            const int slot = i * NTHREADS + t;
            float r =       b0w * cT[j    ][slot];
            r = fmaf(b1w, cT[j + 1][slot], r);
            r = fmaf(b2w, cT[j + 2][slot], r);
            r = fmaf(b3w, cT[j + 3][slot], r);

            if (i == 0) res.x = r; else if (i == 1) res.y = r;
            else if (i == 2) res.z = r; else res.w = r;
        }

        op[(size_t)bi * rowstride4] = res;
    }
}

extern "C" void kernel_launch(void* const* d_in, const int* in_sizes, int n_in,
                              void* d_out, int out_size)
{
    const float* x    = (const float*)d_in[0];
    const float* coef = (const float*)d_in[1];
    const float* grid = (const float*)d_in[2];
    float* out = (float*)d_out;

    const int nspl  = in_sizes[1] / NCOEF;       // coefficients: (S, 8)
    const int batch = in_sizes[0] / nspl;        // x: (B, S)
    const int jmax  = in_sizes[2] - NCOEF;       // (G + 2k + 1) - 8 = G - 1 = 4

    dim3 block(NTHREADS);
    dim3 grd(nspl / TILE_S, batch / TILE_B);
    bspline_kernel<<<grd, block>>>(x, coef, grid, out, nspl, batch, jmax);
}